// round 5
// baseline (speedup 1.0000x reference)
#include <cuda_runtime.h>
#include <math.h>

// SpritesAndTexturesCoordinateDecoder — fused fp32 FFMA2 decoder, v2.
// Output-pair packing: acc[px][jpair] holds outputs (2j, 2j+1) for one pixel.
// Weights staged per-layer in smem, read as uniform LDS.128 (broadcast).
// Activations: scalar floats hact[px][k], row stride 129 (conflict-free).
// Per CTA: 256 pixels, 256 threads, 8 warps = 4 outgroups x 2 pxgroups.
// Per thread: 4 px x 32 outs (acc = 64 ull = 128 regs).

typedef unsigned long long ull;
typedef unsigned int u32;

#define HS 129
#define SM_H     0          // 256*129*4 = 132096
#define SM_W     132096     // 128*128*4 = 65536
#define SM_BIAS  197632     // 512
#define SM_WSH   198144     // 512
#define SM_WT2   198656     // 1536
#define SM_TOTAL 200192

__device__ __align__(16) float g_W0 [32 * 128];    // [k][j], scaled
__device__ __align__(16) float g_W1 [128 * 128];
__device__ __align__(16) float g_W2 [128 * 128];
__device__ __align__(16) float g_Wt0[128 * 128];
__device__ __align__(16) float g_Wt1[128 * 128];
__device__ __align__(16) float g_swt2[3 * 128];    // [c][k], scaled
__device__ __align__(16) float g_swsh[128];
__device__ __align__(16) float g_b0 [8 * 128];
__device__ __align__(16) float g_bt0[8 * 128];

__device__ __forceinline__ ull dup2(float x) {
    ull r; asm("mov.b64 %0, {%1,%1};" : "=l"(r) : "f"(x)); return r;
}
__device__ __forceinline__ float2 unpack2(ull v) {
    float2 f; asm("mov.b64 {%0,%1}, %2;" : "=f"(f.x), "=f"(f.y) : "l"(v)); return f;
}
__device__ __forceinline__ void ffma2(ull& d, ull a, ull b) {
    asm("fma.rn.f32x2 %0, %1, %2, %0;" : "+l"(d) : "l"(a), "l"(b));
}
__device__ __forceinline__ float lrelu_s2(float v) {
    return v > 0.f ? v * 1.4142135623730951f : v * 0.28284271247461907f;
}
// Precise sincos immune to --use_fast_math (args up to ~±80 rad).
__device__ __forceinline__ void my_sincos(float x, float* sp, float* cp) {
    float k = rintf(x * 0.63661977236758134f);
    int   q = (int)k;
    float r = fmaf(k, -1.5707963705062866f, x);
    r       = fmaf(k,  4.3711390001862456e-8f, r);
    float r2 = r * r;
    float p  = fmaf(r2, fmaf(r2, -1.9841271e-4f, 8.3333310e-3f), -1.6666667e-1f);
    float s  = fmaf(p * r2, r, r);
    float qq = fmaf(r2, fmaf(r2, 2.4801587e-5f, -1.3888889e-3f), 4.1666668e-2f);
    float c  = fmaf(qq * r2, r2, fmaf(r2, -0.5f, 1.f));
    int   qm = q & 3;
    float sv = (qm & 1) ? c : s;
    float cv = (qm & 1) ? s : c;
    if (qm == 1 || qm == 2) cv = -cv;
    if (qm == 2 || qm == 3) sv = -sv;
    *sp = sv; *cp = cv;
}

__global__ void prep_kernel(
    const float* __restrict__ ws0, const float* __restrict__ bs0, const float* __restrict__ sc,
    const float* __restrict__ ws1, const float* __restrict__ ws2, const float* __restrict__ wsh,
    const float* __restrict__ wt0, const float* __restrict__ bt0, const float* __restrict__ tc,
    const float* __restrict__ wt1, const float* __restrict__ wt2, int B)
{
    const float s0 = 1.f / sqrtf(96.f), s1 = 1.f / sqrtf(128.f), st0 = 1.f / sqrtf(192.f);
    int nth = blockDim.x * gridDim.x;
    int tid = blockIdx.x * blockDim.x + threadIdx.x;

    for (int idx = tid; idx < 32 * 128; idx += nth) {
        int k = idx >> 7, j = idx & 127;
        g_W0[k * 128 + j] = ws0[j * 96 + k] * s0;
    }
    for (int idx = tid; idx < 128 * 128; idx += nth) {
        int k = idx >> 7, j = idx & 127;
        g_W1 [k * 128 + j] = ws1[j * 128 + k] * s1;
        g_W2 [k * 128 + j] = ws2[j * 128 + k] * s1;
        g_Wt0[k * 128 + j] = wt0[j * 192 + k] * st0;
        g_Wt1[k * 128 + j] = wt1[j * 128 + k] * s1;
    }
    for (int i = tid; i < 128; i += nth) g_swsh[i] = wsh[i] * s1;
    for (int i = tid; i < 384; i += nth) g_swt2[i] = wt2[i] * s1;
    for (int idx = tid; idx < B * 128 && idx < 8 * 128; idx += nth) {
        int b = idx >> 7, j = idx & 127;
        float a = 0.f, t = 0.f;
        for (int m = 0; m < 64; m++) {
            a += sc[b * 64 + m] * ws0[j * 96 + 32 + m];
            t += tc[b * 64 + m] * wt0[j * 192 + 128 + m];
        }
        g_b0 [b * 128 + j] = bs0[j] + a * s0;
        g_bt0[b * 128 + j] = bt0[j] + t * st0;
    }
}

// One layer: acc(4px x 16 jpairs) over K channels; mid-__syncthreads before store.
template <int K>
__device__ __forceinline__ void layer_fn(float* hact, const float* wbuf,
                                         const float* sbias, int og, int pg, int lane)
{
    ull acc[4][16];
    {
        const ulonglong2* bp = (const ulonglong2*)(sbias + og * 32);
#pragma unroll
        for (int jj = 0; jj < 8; jj++) {
            ulonglong2 b = bp[jj];
            acc[0][2*jj] = b.x; acc[1][2*jj] = b.x; acc[2][2*jj] = b.x; acc[3][2*jj] = b.x;
            acc[0][2*jj+1] = b.y; acc[1][2*jj+1] = b.y; acc[2][2*jj+1] = b.y; acc[3][2*jj+1] = b.y;
        }
    }
    const float* h0 = hact + (pg * 128 + lane) * HS;
    const float* wc = wbuf + og * 32;

#pragma unroll 2
    for (int k = 0; k < K; k++) {
        ull a0 = dup2(h0[k]);
        ull a1 = dup2(h0[32 * HS + k]);
        ull a2 = dup2(h0[64 * HS + k]);
        ull a3 = dup2(h0[96 * HS + k]);
        const ulonglong2* w2 = (const ulonglong2*)(wc + k * 128);
#pragma unroll
        for (int jj = 0; jj < 8; jj++) {
            ulonglong2 wp = w2[jj];
            ffma2(acc[0][2*jj], a0, wp.x); ffma2(acc[1][2*jj], a1, wp.x);
            ffma2(acc[2][2*jj], a2, wp.x); ffma2(acc[3][2*jj], a3, wp.x);
            ffma2(acc[0][2*jj+1], a0, wp.y); ffma2(acc[1][2*jj+1], a1, wp.y);
            ffma2(acc[2][2*jj+1], a2, wp.y); ffma2(acc[3][2*jj+1], a3, wp.y);
        }
    }
    __syncthreads();   // all reads of hact + wbuf complete before overwrite
#pragma unroll
    for (int i = 0; i < 4; i++) {
        float* orow = hact + (pg * 128 + i * 32 + lane) * HS + og * 32;
#pragma unroll
        for (int j = 0; j < 16; j++) {
            float2 v = unpack2(acc[i][j]);
            orow[2 * j]     = lrelu_s2(v.x);
            orow[2 * j + 1] = lrelu_s2(v.y);
        }
    }
}

__device__ __forceinline__ void copy_w(float* wbuf, const float* src, int n16, int tid) {
    const uint4* s = (const uint4*)src;
    uint4* d = (uint4*)wbuf;
    for (int i = tid; i < n16; i += 256) d[i] = s[i];
}

__global__ __launch_bounds__(256, 1)
void decoder_kernel(const float* __restrict__ coords,
                    const float* __restrict__ bs1, const float* __restrict__ bs2,
                    const float* __restrict__ bsh, const float* __restrict__ bt1,
                    const float* __restrict__ bt2,
                    float* __restrict__ out, int HW, int BHW)
{
    extern __shared__ char smem[];
    float* hact  = (float*)(smem + SM_H);
    float* wbuf  = (float*)(smem + SM_W);
    float* sbias = (float*)(smem + SM_BIAS);
    float* swsh  = (float*)(smem + SM_WSH);
    float* swt2  = (float*)(smem + SM_WT2);

    int tid = threadIdx.x;
    int lane = tid & 31, wid = tid >> 5;
    int og = wid & 3, pg = wid >> 2;
    int base = blockIdx.x * 256;
    int batch = base / HW;
    int gp = base + tid;
    float bshv = __ldg(bsh);

    for (int i = tid; i < 128; i += 256) { swsh[i] = g_swsh[i]; sbias[i] = g_b0[batch * 128 + i]; }
    for (int i = tid; i < 384; i += 256) swt2[i] = g_swt2[i];
    copy_w(wbuf, g_W0, 1024, tid);

    {   // embedding: 32 channels per pixel, channel 4s+{sinx,siny,cosx,cosy}
        float fx = coords[2 * gp] * 0.1f, fy = coords[2 * gp + 1] * 0.1f;
        float* row = hact + tid * HS;
#pragma unroll
        for (int s = 0; s < 8; s++) {
            float sx, cxv, sy, cyv;
            my_sincos(fx, &sx, &cxv);
            my_sincos(fy, &sy, &cyv);
            row[4 * s + 0] = sx;  row[4 * s + 1] = sy;
            row[4 * s + 2] = cxv; row[4 * s + 3] = cyv;
            fx += fx; fy += fy;
        }
    }
    __syncthreads();

    layer_fn<32>(hact, wbuf, sbias, og, pg, lane);                 // L0
    copy_w(wbuf, g_W1, 4096, tid);
    if (tid < 128) sbias[tid] = bs1[tid];
    __syncthreads();

    layer_fn<128>(hact, wbuf, sbias, og, pg, lane);                // L1
    copy_w(wbuf, g_W2, 4096, tid);
    if (tid < 128) sbias[tid] = bs2[tid];
    __syncthreads();

    layer_fn<128>(hact, wbuf, sbias, og, pg, lane);                // L2
    copy_w(wbuf, g_Wt0, 4096, tid);
    if (tid < 128) sbias[tid] = g_bt0[batch * 128 + tid];
    __syncthreads();

    {   // shape head on L2 output (reads only; next layer's stores are past its mid-sync)
        const float* row = hact + tid * HS;
        float sh = 0.f;
#pragma unroll 8
        for (int k = 0; k < 128; k++) sh = fmaf(row[k], swsh[k], sh);
        float cx = coords[2 * gp], cy = coords[2 * gp + 1];
        float r = sqrtf(cx * cx + cy * cy);
        out[gp] = (sh + bshv) * (1.f - tanhf(fmaxf(r - 1.f, 0.f)));
    }

    layer_fn<128>(hact, wbuf, sbias, og, pg, lane);                // T0
    copy_w(wbuf, g_Wt1, 4096, tid);
    if (tid < 128) sbias[tid] = bt1[tid];
    __syncthreads();

    layer_fn<128>(hact, wbuf, sbias, og, pg, lane);                // T1
    __syncthreads();

    {   // texture head
        const float* row = hact + tid * HS;
        float tA = 0.f, tB = 0.f, tC = 0.f;
#pragma unroll 8
        for (int k = 0; k < 128; k++) {
            float h = row[k];
            tA = fmaf(h, swt2[k], tA);
            tB = fmaf(h, swt2[128 + k], tB);
            tC = fmaf(h, swt2[256 + k], tC);
        }
        float* tp = out + BHW;
        tp[3 * gp + 0] = tA + __ldg(bt2);
        tp[3 * gp + 1] = tB + __ldg(bt2 + 1);
        tp[3 * gp + 2] = tC + __ldg(bt2 + 2);
    }
}

extern "C" void kernel_launch(void* const* d_in, const int* in_sizes, int n_in,
                              void* d_out, int out_size)
{
    const float* coords = (const float*)d_in[0];
    const float* sc  = (const float*)d_in[1];
    const float* tc  = (const float*)d_in[2];
    const float* ws0 = (const float*)d_in[3];  const float* bs0 = (const float*)d_in[4];
    const float* ws1 = (const float*)d_in[5];  const float* bs1 = (const float*)d_in[6];
    const float* ws2 = (const float*)d_in[7];  const float* bs2 = (const float*)d_in[8];
    const float* wsh = (const float*)d_in[9];  const float* bsh = (const float*)d_in[10];
    const float* wt0 = (const float*)d_in[11]; const float* bt0 = (const float*)d_in[12];
    const float* wt1 = (const float*)d_in[13]; const float* bt1 = (const float*)d_in[14];
    const float* wt2 = (const float*)d_in[15]; const float* bt2 = (const float*)d_in[16];
    float* out = (float*)d_out;

    int B   = in_sizes[1] / 64;
    int BHW = in_sizes[0] / 2;
    int HW  = BHW / B;

    prep_kernel<<<64, 256>>>(ws0, bs0, sc, ws1, ws2, wsh, wt0, bt0, tc, wt1, wt2, B);

    cudaFuncSetAttribute(decoder_kernel, cudaFuncAttributeMaxDynamicSharedMemorySize, SM_TOTAL);
    decoder_kernel<<<BHW / 256, 256, SM_TOTAL>>>(coords, bs1, bs2, bsh, bt1, bt2, out, HW, BHW);
}

// round 6
// speedup vs baseline: 1.9708x; 1.9708x over previous
#include <cuda_runtime.h>
#include <math.h>

// SpritesAndTexturesCoordinateDecoder — bf16 split-precision mma.sync decoder.
// Per warp: 16 pixels, all 128 channels in registers; layers chain via the
// D(2 n-tiles) == A(1 k-tile) fragment identity. Weights are pre-packed
// B-fragments (hi/lo) double-buffered in smem.

typedef unsigned int u32; typedef unsigned short u16;

__device__ __align__(16) uint4 g_Bfrag[5][4096];   // [layer][(ks*16+nt)*32+lane] {hiB0,hiB1,loB0,loB1}
__device__ float g_b0[8 * 128], g_bt0[8 * 128];
__device__ float g_swsh[128], g_swt2[384];

#define SLOT0 0
#define SLOT1 65536
#define SBIAS 131072    // 2 x 512 B
#define SWSH  132096
#define SWT2  132608
#define SMTOT 134144

__device__ __forceinline__ float lrelu_s2(float v) {
    return v > 0.f ? v * 1.4142135623730951f : v * 0.28284271247461907f;
}
__device__ __forceinline__ void my_sincos(float x, float* sp, float* cp) {
    float k = rintf(x * 0.63661977236758134f);
    int   q = (int)k;
    float r = fmaf(k, -1.5707963705062866f, x);
    r       = fmaf(k,  4.3711390001862456e-8f, r);
    float r2 = r * r;
    float p  = fmaf(r2, fmaf(r2, -1.9841271e-4f, 8.3333310e-3f), -1.6666667e-1f);
    float s  = fmaf(p * r2, r, r);
    float qq = fmaf(r2, fmaf(r2, 2.4801587e-5f, -1.3888889e-3f), 4.1666668e-2f);
    float c  = fmaf(qq * r2, r2, fmaf(r2, -0.5f, 1.f));
    int   qm = q & 3;
    float sv = (qm & 1) ? c : s;
    float cv = (qm & 1) ? s : c;
    if (qm == 1 || qm == 2) cv = -cv;
    if (qm == 2 || qm == 3) sv = -sv;
    *sp = sv; *cp = cv;
}
__device__ __forceinline__ u32 bfbits32(float v) {
    u32 r; asm("{ .reg .b16 h; cvt.rn.bf16.f32 h, %1; mov.b32 %0, {h, 0}; }" : "=r"(r) : "f"(v));
    return r & 0xFFFFu;
}

// D/C += A x B  (m16n8k16, bf16 in, f32 acc)
__device__ __forceinline__ void mma4(float* c, const u32* a, u32 b0, u32 b1) {
    asm volatile("mma.sync.aligned.m16n8k16.row.col.f32.bf16.bf16.f32 "
                 "{%0,%1,%2,%3}, {%4,%5,%6,%7}, {%8,%9}, {%0,%1,%2,%3};"
                 : "+f"(c[0]), "+f"(c[1]), "+f"(c[2]), "+f"(c[3])
                 : "r"(a[0]), "r"(a[1]), "r"(a[2]), "r"(a[3]), "r"(b0), "r"(b1));
}

// split two fp32 into packed bf16x2 hi (truncation) + bf16x2 lo (v - hi)
__device__ __forceinline__ void split2(float v0, float v1, u32& hi, u32& lo) {
    u32 u0 = __float_as_uint(v0), u1 = __float_as_uint(v1);
    hi = __byte_perm(u0, u1, 0x7632);
    float l0 = v0 - __uint_as_float(u0 & 0xFFFF0000u);
    float l1 = v1 - __uint_as_float(u1 & 0xFFFF0000u);
    asm("cvt.rn.bf16x2.f32 %0, %1, %2;" : "=r"(lo) : "f"(l1), "f"(l0));
}

// MODE: 0 normal, 1 = L2 (also shape partials), 2 = last (texture partials, no split)
template <int NKS, int MODE>
__device__ __forceinline__ void run_layer(const uint4* __restrict__ wslot,
                                          const float* __restrict__ bias,
                                          u32 (&ah)[8][4], u32 (&al)[8][4],
                                          int lane, int q,
                                          float* hp, const float* swsh, const float* swt2)
{
    float acc[16][4];
#pragma unroll
    for (int nt = 0; nt < 16; nt++) {
        float2 b = *(const float2*)(bias + nt * 8 + 2 * q);
        acc[nt][0] = b.x; acc[nt][1] = b.y; acc[nt][2] = b.x; acc[nt][3] = b.y;
    }
#pragma unroll
    for (int ks = 0; ks < NKS; ks++) {
#pragma unroll
        for (int nt = 0; nt < 16; nt++) {
            uint4 f = wslot[(ks * 16 + nt) * 32 + lane];
            mma4(acc[nt], ah[ks], f.x, f.y);   // hiA * hiB
            mma4(acc[nt], ah[ks], f.z, f.w);   // hiA * loB
            mma4(acc[nt], al[ks], f.x, f.y);   // loA * hiB
        }
    }
#pragma unroll
    for (int nt = 0; nt < 16; nt++) {
        float v0 = lrelu_s2(acc[nt][0]), v1 = lrelu_s2(acc[nt][1]);
        float v2 = lrelu_s2(acc[nt][2]), v3 = lrelu_s2(acc[nt][3]);
        int ch = nt * 8 + 2 * q;
        if (MODE == 1) {
            hp[0] = fmaf(v0, swsh[ch], fmaf(v1, swsh[ch + 1], hp[0]));
            hp[1] = fmaf(v2, swsh[ch], fmaf(v3, swsh[ch + 1], hp[1]));
        }
        if (MODE == 2) {
#pragma unroll
            for (int c = 0; c < 3; c++) {
                hp[2 * c]     = fmaf(v0, swt2[c * 128 + ch], fmaf(v1, swt2[c * 128 + ch + 1], hp[2 * c]));
                hp[2 * c + 1] = fmaf(v2, swt2[c * 128 + ch], fmaf(v3, swt2[c * 128 + ch + 1], hp[2 * c + 1]));
            }
        } else {
            int ks2 = nt >> 1, hf = nt & 1;
            split2(v0, v1, ah[ks2][2 * hf],     al[ks2][2 * hf]);
            split2(v2, v3, ah[ks2][2 * hf + 1], al[ks2][2 * hf + 1]);
        }
    }
}

__device__ __forceinline__ void copy16(char* smem, int slot, const uint4* src, int n, int tid) {
    uint4* d = (uint4*)(smem + slot);
    for (int i = tid; i < n; i += 256) d[i] = src[i];
}

__global__ void prep_kernel(
    const float* __restrict__ ws0, const float* __restrict__ bs0, const float* __restrict__ sc,
    const float* __restrict__ ws1, const float* __restrict__ ws2, const float* __restrict__ wsh,
    const float* __restrict__ wt0, const float* __restrict__ bt0, const float* __restrict__ tc,
    const float* __restrict__ wt1, const float* __restrict__ wt2, int B)
{
    const float s0 = 1.f / sqrtf(96.f), s1 = 1.f / sqrtf(128.f), st0 = 1.f / sqrtf(192.f);
    int nth = blockDim.x * gridDim.x;
    int tid0 = blockIdx.x * blockDim.x + threadIdx.x;

    for (int l = 0; l < 5; l++) {
        int KS; const float* src; float scl; int srcw;
        if      (l == 0) { KS = 2; src = ws0; scl = s0;  srcw = 96;  }
        else if (l == 1) { KS = 8; src = ws1; scl = s1;  srcw = 128; }
        else if (l == 2) { KS = 8; src = ws2; scl = s1;  srcw = 128; }
        else if (l == 3) { KS = 8; src = wt0; scl = st0; srcw = 192; }
        else             { KS = 8; src = wt1; scl = s1;  srcw = 128; }
        int tot = KS * 512;
        for (int idx = tid0; idx < tot; idx += nth) {
            int ks = idx >> 9, rem = idx & 511, nt = rem >> 5, lane = rem & 31;
            int q = lane & 3, gg = lane >> 2;
            int n = nt * 8 + gg;
            int ka = ks * 16 + 2 * q;
            float w[4];
            w[0] = src[n * srcw + ka] * scl;
            w[1] = src[n * srcw + ka + 1] * scl;
            w[2] = src[n * srcw + ka + 8] * scl;
            w[3] = src[n * srcw + ka + 9] * scl;
            u32 h[4], lo[4];
            for (int i = 0; i < 4; i++) {
                u32 ub = __float_as_uint(w[i]) & 0xFFFF0000u;  // truncation split
                h[i] = ub >> 16;
                lo[i] = bfbits32(w[i] - __uint_as_float(ub));
            }
            uint4 f;
            f.x = h[0] | (h[1] << 16);
            f.y = h[2] | (h[3] << 16);
            f.z = lo[0] | (lo[1] << 16);
            f.w = lo[2] | (lo[3] << 16);
            g_Bfrag[l][(ks * 16 + nt) * 32 + lane] = f;
        }
    }
    for (int i = tid0; i < 128; i += nth) g_swsh[i] = wsh[i] * s1;
    for (int i = tid0; i < 384; i += nth) g_swt2[i] = wt2[i] * s1;
    for (int idx = tid0; idx < B * 128 && idx < 8 * 128; idx += nth) {
        int b = idx >> 7, j = idx & 127;
        float a = 0.f, t = 0.f;
        for (int m = 0; m < 64; m++) {
            a += sc[b * 64 + m] * ws0[j * 96 + 32 + m];
            t += tc[b * 64 + m] * wt0[j * 192 + 128 + m];
        }
        g_b0 [b * 128 + j] = bs0[j] + a * s0;
        g_bt0[b * 128 + j] = bt0[j] + t * st0;
    }
}

__global__ __launch_bounds__(256, 1)
void decoder_kernel(const float* __restrict__ coords,
                    const float* __restrict__ bs1, const float* __restrict__ bs2,
                    const float* __restrict__ bsh, const float* __restrict__ bt1,
                    const float* __restrict__ bt2,
                    float* __restrict__ out, int HW, int BHW)
{
    extern __shared__ char smem[];
    const uint4* slot0 = (const uint4*)(smem + SLOT0);
    const uint4* slot1 = (const uint4*)(smem + SLOT1);
    float* sbias0 = (float*)(smem + SBIAS);
    float* sbias1 = sbias0 + 128;
    float* swsh   = (float*)(smem + SWSH);
    float* swt2   = (float*)(smem + SWT2);

    int tid = threadIdx.x;
    int lane = tid & 31, w = tid >> 5;
    int q = lane & 3, g = lane >> 2;
    int base = blockIdx.x * 128;
    int batch = base / HW;
    int px0 = base + w * 16 + g, px1 = px0 + 8;

    float2 crd0 = ((const float2*)coords)[px0];
    float2 crd1 = ((const float2*)coords)[px1];

    // ---- embedding -> A fragments for L0 (K=32 => ksteps 0,1)
    u32 ah[8][4], al[8][4];
#pragma unroll
    for (int ks = 0; ks < 2; ks++) {
#pragma unroll
        for (int h = 0; h < 2; h++) {
            int s = 4 * ks + 2 * h + (q >> 1);
            float scl = 0.1f * (float)(1 << s);
#pragma unroll
            for (int row = 0; row < 2; row++) {
                float cx = (row ? crd1.x : crd0.x) * scl;
                float cy = (row ? crd1.y : crd0.y) * scl;
                float sx, cxv, sy, cyv;
                my_sincos(cx, &sx, &cxv);
                my_sincos(cy, &sy, &cyv);
                float v0 = (q & 1) ? cxv : sx;
                float v1 = (q & 1) ? cyv : sy;
                split2(v0, v1, ah[ks][2 * h + row], al[ks][2 * h + row]);
            }
        }
    }

    // ---- stage L0 weights + bias + heads
    copy16(smem, SLOT0, g_Bfrag[0], 1024, tid);
    if (tid < 128) { sbias0[tid] = g_b0[batch * 128 + tid]; swsh[tid] = g_swsh[tid]; }
    for (int i = tid; i < 384; i += 256) swt2[i] = g_swt2[i];
    __syncthreads();

    float dummy[1];
    // L0 (prefetch L1)
    copy16(smem, SLOT1, g_Bfrag[1], 4096, tid);
    if (tid < 128) sbias1[tid] = bs1[tid];
    run_layer<2, 0>(slot0, sbias0, ah, al, lane, q, dummy, swsh, swt2);
    __syncthreads();

    // L1 (prefetch L2)
    copy16(smem, SLOT0, g_Bfrag[2], 4096, tid);
    if (tid < 128) sbias0[tid] = bs2[tid];
    run_layer<8, 0>(slot1, sbias1, ah, al, lane, q, dummy, swsh, swt2);
    __syncthreads();

    // L2: shape head partials (prefetch T0)
    copy16(smem, SLOT1, g_Bfrag[3], 4096, tid);
    if (tid < 128) sbias1[tid] = g_bt0[batch * 128 + tid];
    float pS[2] = {0.f, 0.f};
    run_layer<8, 1>(slot0, sbias0, ah, al, lane, q, pS, swsh, swt2);
    // quad reduce + shape write
    {
        pS[0] += __shfl_xor_sync(0xffffffffu, pS[0], 1);
        pS[0] += __shfl_xor_sync(0xffffffffu, pS[0], 2);
        pS[1] += __shfl_xor_sync(0xffffffffu, pS[1], 1);
        pS[1] += __shfl_xor_sync(0xffffffffu, pS[1], 2);
        if (q == 0) {
            float bv = __ldg(bsh);
            float r0 = sqrtf(crd0.x * crd0.x + crd0.y * crd0.y);
            float r1 = sqrtf(crd1.x * crd1.x + crd1.y * crd1.y);
            out[px0] = (pS[0] + bv) * (1.f - tanhf(fmaxf(r0 - 1.f, 0.f)));
            out[px1] = (pS[1] + bv) * (1.f - tanhf(fmaxf(r1 - 1.f, 0.f)));
        }
    }
    __syncthreads();

    // T0 (prefetch T1)
    copy16(smem, SLOT0, g_Bfrag[4], 4096, tid);
    if (tid < 128) sbias0[tid] = bt1[tid];
    run_layer<8, 0>(slot1, sbias1, ah, al, lane, q, dummy, swsh, swt2);
    __syncthreads();

    // T1: texture head partials
    float pT[6] = {0.f, 0.f, 0.f, 0.f, 0.f, 0.f};
    run_layer<8, 2>(slot0, sbias0, ah, al, lane, q, pT, swsh, swt2);
    {
#pragma unroll
        for (int i = 0; i < 6; i++) {
            pT[i] += __shfl_xor_sync(0xffffffffu, pT[i], 1);
            pT[i] += __shfl_xor_sync(0xffffffffu, pT[i], 2);
        }
        if (q == 0) {
            float* tp = out + BHW;
#pragma unroll
            for (int c = 0; c < 3; c++) {
                float bv = __ldg(bt2 + c);
                tp[3 * px0 + c] = pT[2 * c] + bv;
                tp[3 * px1 + c] = pT[2 * c + 1] + bv;
            }
        }
    }
}

extern "C" void kernel_launch(void* const* d_in, const int* in_sizes, int n_in,
                              void* d_out, int out_size)
{
    const float* coords = (const float*)d_in[0];
    const float* sc  = (const float*)d_in[1];
    const float* tc  = (const float*)d_in[2];
    const float* ws0 = (const float*)d_in[3];  const float* bs0 = (const float*)d_in[4];
    const float* ws1 = (const float*)d_in[5];  const float* bs1 = (const float*)d_in[6];
    const float* ws2 = (const float*)d_in[7];  const float* bs2 = (const float*)d_in[8];
    const float* wsh = (const float*)d_in[9];  const float* bsh = (const float*)d_in[10];
    const float* wt0 = (const float*)d_in[11]; const float* bt0 = (const float*)d_in[12];
    const float* wt1 = (const float*)d_in[13]; const float* bt1 = (const float*)d_in[14];
    const float* wt2 = (const float*)d_in[15]; const float* bt2 = (const float*)d_in[16];
    float* out = (float*)d_out;

    int B   = in_sizes[1] / 64;
    int BHW = in_sizes[0] / 2;
    int HW  = BHW / B;

    prep_kernel<<<64, 256>>>(ws0, bs0, sc, ws1, ws2, wsh, wt0, bt0, tc, wt1, wt2, B);

    cudaFuncSetAttribute(decoder_kernel, cudaFuncAttributeMaxDynamicSharedMemorySize, SMTOT);
    decoder_kernel<<<BHW / 128, 256, SMTOT>>>(coords, bs1, bs2, bsh, bt1, bt2, out, HW, BHW);
}

// round 7
// speedup vs baseline: 3.2554x; 1.6518x over previous
#include <cuda_runtime.h>
#include <math.h>

// SpritesAndTexturesCoordinateDecoder — bf16 split-precision mma.sync decoder, v2.
// Warp-autonomous: no smem, no syncthreads. Weights read as pre-packed
// B-fragments straight from global (L1-resident, shared by all warps).
// Per warp: 16 pixels, all 128 channels chained in registers across 5 layers.

typedef unsigned int u32;

__device__ __align__(16) uint4 g_Bfrag[5][4096];   // [layer][(ks*16+nt)*32+lane] {hiB0,hiB1,loB0,loB1}
__device__ float g_b0[8 * 128], g_bt0[8 * 128];
__device__ float g_swsh[128], g_swt2[384];

__device__ __forceinline__ float lrelu_s2(float v) {
    return v > 0.f ? v * 1.4142135623730951f : v * 0.28284271247461907f;
}
__device__ __forceinline__ void my_sincos(float x, float* sp, float* cp) {
    float k = rintf(x * 0.63661977236758134f);
    int   q = (int)k;
    float r = fmaf(k, -1.5707963705062866f, x);
    r       = fmaf(k,  4.3711390001862456e-8f, r);
    float r2 = r * r;
    float p  = fmaf(r2, fmaf(r2, -1.9841271e-4f, 8.3333310e-3f), -1.6666667e-1f);
    float s  = fmaf(p * r2, r, r);
    float qq = fmaf(r2, fmaf(r2, 2.4801587e-5f, -1.3888889e-3f), 4.1666668e-2f);
    float c  = fmaf(qq * r2, r2, fmaf(r2, -0.5f, 1.f));
    int   qm = q & 3;
    float sv = (qm & 1) ? c : s;
    float cv = (qm & 1) ? s : c;
    if (qm == 1 || qm == 2) cv = -cv;
    if (qm == 2 || qm == 3) sv = -sv;
    *sp = sv; *cp = cv;
}
__device__ __forceinline__ u32 bfbits32(float v) {
    u32 r; asm("{ .reg .b16 h; cvt.rn.bf16.f32 h, %1; mov.b32 %0, {h, 0}; }" : "=r"(r) : "f"(v));
    return r & 0xFFFFu;
}
// D/C += A x B  (m16n8k16, bf16 in, f32 acc)
__device__ __forceinline__ void mma4(float* c, const u32* a, u32 b0, u32 b1) {
    asm("mma.sync.aligned.m16n8k16.row.col.f32.bf16.bf16.f32 "
        "{%0,%1,%2,%3}, {%4,%5,%6,%7}, {%8,%9}, {%0,%1,%2,%3};"
        : "+f"(c[0]), "+f"(c[1]), "+f"(c[2]), "+f"(c[3])
        : "r"(a[0]), "r"(a[1]), "r"(a[2]), "r"(a[3]), "r"(b0), "r"(b1));
}
// split two fp32 into packed bf16x2 hi (truncation) + bf16x2 lo (v - hi)
__device__ __forceinline__ void split2(float v0, float v1, u32& hi, u32& lo) {
    u32 u0 = __float_as_uint(v0), u1 = __float_as_uint(v1);
    hi = __byte_perm(u0, u1, 0x7632);
    float l0 = v0 - __uint_as_float(u0 & 0xFFFF0000u);
    float l1 = v1 - __uint_as_float(u1 & 0xFFFF0000u);
    asm("cvt.rn.bf16x2.f32 %0, %1, %2;" : "=r"(lo) : "f"(l1), "f"(l0));
}

// MODE: 0 normal, 1 = L2 (shape partials), 2 = last (texture partials, no split)
template <int NKS, int MODE>
__device__ __forceinline__ void run_layer(const uint4* __restrict__ wfrag,
                                          const float* __restrict__ bias,
                                          u32 (&ah)[8][4], u32 (&al)[8][4],
                                          int lane, int q, float* hp)
{
    float acc[16][4];
#pragma unroll
    for (int nt = 0; nt < 16; nt++) {
        float2 b = __ldg((const float2*)(bias + nt * 8 + 2 * q));
        acc[nt][0] = b.x; acc[nt][1] = b.y; acc[nt][2] = b.x; acc[nt][3] = b.y;
    }
#pragma unroll
    for (int ks = 0; ks < NKS; ks++) {
#pragma unroll
        for (int nt = 0; nt < 16; nt++) {
            uint4 f = __ldg(&wfrag[(ks * 16 + nt) * 32 + lane]);
            mma4(acc[nt], ah[ks], f.x, f.y);   // hiA * hiB
            mma4(acc[nt], ah[ks], f.z, f.w);   // hiA * loB
            mma4(acc[nt], al[ks], f.x, f.y);   // loA * hiB
        }
    }
#pragma unroll
    for (int nt = 0; nt < 16; nt++) {
        float v0 = lrelu_s2(acc[nt][0]), v1 = lrelu_s2(acc[nt][1]);
        float v2 = lrelu_s2(acc[nt][2]), v3 = lrelu_s2(acc[nt][3]);
        int ch = nt * 8 + 2 * q;
        if (MODE == 1) {
            float2 wv = __ldg((const float2*)(g_swsh + ch));
            hp[0] = fmaf(v0, wv.x, fmaf(v1, wv.y, hp[0]));
            hp[1] = fmaf(v2, wv.x, fmaf(v3, wv.y, hp[1]));
        }
        if (MODE == 2) {
#pragma unroll
            for (int c = 0; c < 3; c++) {
                float2 wv = __ldg((const float2*)(g_swt2 + c * 128 + ch));
                hp[2 * c]     = fmaf(v0, wv.x, fmaf(v1, wv.y, hp[2 * c]));
                hp[2 * c + 1] = fmaf(v2, wv.x, fmaf(v3, wv.y, hp[2 * c + 1]));
            }
        } else {
            int ks2 = nt >> 1, hf = nt & 1;
            split2(v0, v1, ah[ks2][2 * hf],     al[ks2][2 * hf]);
            split2(v2, v3, ah[ks2][2 * hf + 1], al[ks2][2 * hf + 1]);
        }
    }
}

__global__ void prep_kernel(
    const float* __restrict__ ws0, const float* __restrict__ bs0, const float* __restrict__ sc,
    const float* __restrict__ ws1, const float* __restrict__ ws2, const float* __restrict__ wsh,
    const float* __restrict__ wt0, const float* __restrict__ bt0, const float* __restrict__ tc,
    const float* __restrict__ wt1, const float* __restrict__ wt2, int B)
{
    const float s0 = 1.f / sqrtf(96.f), s1 = 1.f / sqrtf(128.f), st0 = 1.f / sqrtf(192.f);
    int nth = blockDim.x * gridDim.x;
    int tid0 = blockIdx.x * blockDim.x + threadIdx.x;

    for (int l = 0; l < 5; l++) {
        int KS; const float* src; float scl; int srcw;
        if      (l == 0) { KS = 2; src = ws0; scl = s0;  srcw = 96;  }
        else if (l == 1) { KS = 8; src = ws1; scl = s1;  srcw = 128; }
        else if (l == 2) { KS = 8; src = ws2; scl = s1;  srcw = 128; }
        else if (l == 3) { KS = 8; src = wt0; scl = st0; srcw = 192; }
        else             { KS = 8; src = wt1; scl = s1;  srcw = 128; }
        int tot = KS * 512;
        for (int idx = tid0; idx < tot; idx += nth) {
            int ks = idx >> 9, rem = idx & 511, nt = rem >> 5, lane = rem & 31;
            int q = lane & 3, gg = lane >> 2;
            int n = nt * 8 + gg;
            int ka = ks * 16 + 2 * q;
            float w[4];
            w[0] = src[n * srcw + ka] * scl;
            w[1] = src[n * srcw + ka + 1] * scl;
            w[2] = src[n * srcw + ka + 8] * scl;
            w[3] = src[n * srcw + ka + 9] * scl;
            u32 h[4], lo[4];
            for (int i = 0; i < 4; i++) {
                u32 ub = __float_as_uint(w[i]) & 0xFFFF0000u;
                h[i] = ub >> 16;
                lo[i] = bfbits32(w[i] - __uint_as_float(ub));
            }
            uint4 f;
            f.x = h[0] | (h[1] << 16);
            f.y = h[2] | (h[3] << 16);
            f.z = lo[0] | (lo[1] << 16);
            f.w = lo[2] | (lo[3] << 16);
            g_Bfrag[l][(ks * 16 + nt) * 32 + lane] = f;
        }
    }
    for (int i = tid0; i < 128; i += nth) g_swsh[i] = wsh[i] * s1;
    for (int i = tid0; i < 384; i += nth) g_swt2[i] = wt2[i] * s1;
    for (int idx = tid0; idx < B * 128 && idx < 8 * 128; idx += nth) {
        int b = idx >> 7, j = idx & 127;
        float a = 0.f, t = 0.f;
        for (int m = 0; m < 64; m++) {
            a += sc[b * 64 + m] * ws0[j * 96 + 32 + m];
            t += tc[b * 64 + m] * wt0[j * 192 + 128 + m];
        }
        g_b0 [b * 128 + j] = bs0[j] + a * s0;
        g_bt0[b * 128 + j] = bt0[j] + t * st0;
    }
}

__global__ __launch_bounds__(128, 3)
void decoder_kernel(const float* __restrict__ coords,
                    const float* __restrict__ bs1, const float* __restrict__ bs2,
                    const float* __restrict__ bsh, const float* __restrict__ bt1,
                    const float* __restrict__ bt2,
                    float* __restrict__ out, int HW, int BHW)
{
    int tid = threadIdx.x;
    int lane = tid & 31, w = tid >> 5;
    int q = lane & 3, g = lane >> 2;
    int base = blockIdx.x * 64;          // 4 warps x 16 px
    int batch = base / HW;
    int px0 = base + w * 16 + g, px1 = px0 + 8;

    float2 crd0 = __ldg(&((const float2*)coords)[px0]);
    float2 crd1 = __ldg(&((const float2*)coords)[px1]);

    // ---- embedding -> A fragments for L0 (K=32 => ksteps 0,1)
    u32 ah[8][4], al[8][4];
#pragma unroll
    for (int ks = 0; ks < 2; ks++) {
#pragma unroll
        for (int h = 0; h < 2; h++) {
            int s = 4 * ks + 2 * h + (q >> 1);
            float scl = 0.1f * (float)(1 << s);
#pragma unroll
            for (int row = 0; row < 2; row++) {
                float cx = (row ? crd1.x : crd0.x) * scl;
                float cy = (row ? crd1.y : crd0.y) * scl;
                float sx, cxv, sy, cyv;
                my_sincos(cx, &sx, &cxv);
                my_sincos(cy, &sy, &cyv);
                float v0 = (q & 1) ? cxv : sx;
                float v1 = (q & 1) ? cyv : sy;
                split2(v0, v1, ah[ks][2 * h + row], al[ks][2 * h + row]);
            }
        }
    }

    float dummy[1];
    run_layer<2, 0>(g_Bfrag[0], g_b0 + batch * 128, ah, al, lane, q, dummy);   // L0
    run_layer<8, 0>(g_Bfrag[1], bs1,                ah, al, lane, q, dummy);   // L1

    // L2 + shape head partials
    float pS[2] = {0.f, 0.f};
    run_layer<8, 1>(g_Bfrag[2], bs2, ah, al, lane, q, pS);
    {
        pS[0] += __shfl_xor_sync(0xffffffffu, pS[0], 1);
        pS[0] += __shfl_xor_sync(0xffffffffu, pS[0], 2);
        pS[1] += __shfl_xor_sync(0xffffffffu, pS[1], 1);
        pS[1] += __shfl_xor_sync(0xffffffffu, pS[1], 2);
        if (q == 0) {
            float bv = __ldg(bsh);
            float r0 = sqrtf(crd0.x * crd0.x + crd0.y * crd0.y);
            float r1 = sqrtf(crd1.x * crd1.x + crd1.y * crd1.y);
            out[px0] = (pS[0] + bv) * (1.f - tanhf(fmaxf(r0 - 1.f, 0.f)));
            out[px1] = (pS[1] + bv) * (1.f - tanhf(fmaxf(r1 - 1.f, 0.f)));
        }
    }

    run_layer<8, 0>(g_Bfrag[3], g_bt0 + batch * 128, ah, al, lane, q, dummy);  // T0

    // T1 + texture head partials
    float pT[6] = {0.f, 0.f, 0.f, 0.f, 0.f, 0.f};
    run_layer<8, 2>(g_Bfrag[4], bt1, ah, al, lane, q, pT);
    {
#pragma unroll
        for (int i = 0; i < 6; i++) {
            pT[i] += __shfl_xor_sync(0xffffffffu, pT[i], 1);
            pT[i] += __shfl_xor_sync(0xffffffffu, pT[i], 2);
        }
        if (q == 0) {
            float* tp = out + BHW;
#pragma unroll
            for (int c = 0; c < 3; c++) {
                float bv = __ldg(bt2 + c);
                tp[3 * px0 + c] = pT[2 * c] + bv;
                tp[3 * px1 + c] = pT[2 * c + 1] + bv;
            }
        }
    }
}

extern "C" void kernel_launch(void* const* d_in, const int* in_sizes, int n_in,
                              void* d_out, int out_size)
{
    const float* coords = (const float*)d_in[0];
    const float* sc  = (const float*)d_in[1];
    const float* tc  = (const float*)d_in[2];
    const float* ws0 = (const float*)d_in[3];  const float* bs0 = (const float*)d_in[4];
    const float* ws1 = (const float*)d_in[5];  const float* bs1 = (const float*)d_in[6];
    const float* ws2 = (const float*)d_in[7];  const float* bs2 = (const float*)d_in[8];
    const float* wsh = (const float*)d_in[9];  const float* bsh = (const float*)d_in[10];
    const float* wt0 = (const float*)d_in[11]; const float* bt0 = (const float*)d_in[12];
    const float* wt1 = (const float*)d_in[13]; const float* bt1 = (const float*)d_in[14];
    const float* wt2 = (const float*)d_in[15]; const float* bt2 = (const float*)d_in[16];
    float* out = (float*)d_out;

    int B   = in_sizes[1] / 64;
    int BHW = in_sizes[0] / 2;
    int HW  = BHW / B;

    prep_kernel<<<64, 256>>>(ws0, bs0, sc, ws1, ws2, wsh, wt0, bt0, tc, wt1, wt2, B);
    decoder_kernel<<<BHW / 64, 128>>>(coords, bs1, bs2, bsh, bt1, bt2, out, HW, BHW);
}